// round 8
// baseline (speedup 1.0000x reference)
#include <cuda_runtime.h>
#include <cuda_fp16.h>
#include <math.h>
#include <stdint.h>

// Problem dims
#define BATCH 2
#define SEQ   2048
#define DIM   2048
#define NSTATE 16
#define TOKENS (BATCH*SEQ)        // 4096
#define TWO_DIM (2*DIM)           // 4096
#define LN_EPS 1e-5f

// -------------------- scratch (device globals, allocation-free) ------------
__device__ __half g_xn[TOKENS * DIM];
__device__ __half g_xz[TOKENS * TWO_DIM];
__device__ __half g_dt[TOKENS * DIM];
__device__ __half g_gated[TOKENS * DIM];
__device__ __half g_win [TWO_DIM * DIM];
__device__ __half g_wdt [DIM * DIM];
__device__ __half g_wout[DIM * DIM];
__device__ float  g_apow[3 * NSTATE * DIM];   // [(n*3+k)][d]: A, A^2/2, A^3/6

// -------------------- helpers ----------------------------------------------
__device__ __forceinline__ void cp_async16(void* smem, const void* gmem) {
    unsigned s = (unsigned)__cvta_generic_to_shared(smem);
    asm volatile("cp.async.cg.shared.global [%0], [%1], 16;\n" :: "r"(s), "l"(gmem));
}
__device__ __forceinline__ void mma_fp16(float* c, const unsigned* a, const unsigned* b) {
    asm volatile(
        "mma.sync.aligned.m16n8k16.row.col.f32.f16.f16.f32 "
        "{%0,%1,%2,%3}, {%4,%5,%6,%7}, {%8,%9}, {%0,%1,%2,%3};"
        : "+f"(c[0]), "+f"(c[1]), "+f"(c[2]), "+f"(c[3])
        : "r"(a[0]), "r"(a[1]), "r"(a[2]), "r"(a[3]), "r"(b[0]), "r"(b[1]));
}
__device__ __forceinline__ void ldmatrix_x4(unsigned* r, unsigned saddr) {
    asm volatile("ldmatrix.sync.aligned.m8n8.x4.shared.b16 {%0,%1,%2,%3}, [%4];"
                 : "=r"(r[0]), "=r"(r[1]), "=r"(r[2]), "=r"(r[3]) : "r"(saddr));
}

// -------------------- FP16 tensor-core GEMM (unchanged from R6) -------------
#define BM 128
#define BN 128
#define BKH 32
#define STAGES 3
#define HROW 40
#define TILE_H (BM * HROW)
#define SM_TOTAL_BYTES (2 * STAGES * TILE_H * 2)   // 61440

template<int EPI, int OUTH>
__global__ void __launch_bounds__(256, 2) gemm_fp16(
    const __half* __restrict__ A, int lda,
    const __half* __restrict__ B, int ldb,
    const float* __restrict__ bias,
    const float* __restrict__ res, int ldres,
    void* __restrict__ Cv, int ldc,
    int K)
{
    extern __shared__ __half sm[];
    #define AS(s, r, c) sm[(s) * TILE_H + (r) * HROW + (c)]
    #define BS(s, r, c) sm[STAGES * TILE_H + (s) * TILE_H + (r) * HROW + (c)]

    const int bm = blockIdx.y * BM;
    const int bn = blockIdx.x * BN;
    const int tid = threadIdx.x;
    const int wid = tid >> 5;
    const int lane = tid & 31;
    const int g = lane >> 2;
    const int t = lane & 3;

    const int warp_m = wid >> 2;
    const int warp_n = wid & 3;
    const int m0 = warp_m * 64;
    const int n0 = warp_n * 32;

    const unsigned smem_base = (unsigned)__cvta_generic_to_shared(sm);
    const int lane16 = lane & 15;
    const int lhalf  = lane >> 4;
    unsigned aoff[4], boff[2];
    #pragma unroll
    for (int mt = 0; mt < 4; mt++)
        aoff[mt] = smem_base + ((m0 + mt * 16 + lane16) * HROW + lhalf * 8) * 2;
    #pragma unroll
    for (int np = 0; np < 2; np++)
        boff[np] = smem_base + (STAGES * TILE_H + (n0 + np * 16 + lane16) * HROW + lhalf * 8) * 2;

    const int ar = tid >> 2;
    const int ac = (tid & 3) * 8;

    const __half* Ag = A + (size_t)(bm + ar) * lda + ac;
    const __half* Bg = B + (size_t)(bn + ar) * ldb + ac;

    float acc[4][4][4];
    #pragma unroll
    for (int i = 0; i < 4; i++)
        #pragma unroll
        for (int j = 0; j < 4; j++)
            #pragma unroll
            for (int r = 0; r < 4; r++) acc[i][j][r] = 0.f;

    const int NCH = K / BKH;

    #pragma unroll
    for (int c = 0; c < STAGES - 1; c++) {
        cp_async16(&AS(c, ar, ac),      Ag + c * BKH);
        cp_async16(&AS(c, ar + 64, ac), Ag + c * BKH + (size_t)64 * lda);
        cp_async16(&BS(c, ar, ac),      Bg + c * BKH);
        cp_async16(&BS(c, ar + 64, ac), Bg + c * BKH + (size_t)64 * ldb);
        asm volatile("cp.async.commit_group;\n" ::: "memory");
    }

    int cur = 0, nxt = STAGES - 1;
    for (int k = 0; k < NCH; k++) {
        asm volatile("cp.async.wait_group %0;\n" :: "n"(STAGES - 2) : "memory");
        __syncthreads();

        const int j = k + STAGES - 1;
        if (j < NCH) {
            cp_async16(&AS(nxt, ar, ac),      Ag + j * BKH);
            cp_async16(&AS(nxt, ar + 64, ac), Ag + j * BKH + (size_t)64 * lda);
            cp_async16(&BS(nxt, ar, ac),      Bg + j * BKH);
            cp_async16(&BS(nxt, ar + 64, ac), Bg + j * BKH + (size_t)64 * ldb);
        }
        asm volatile("cp.async.commit_group;\n" ::: "memory");

        const unsigned stage_off = cur * TILE_H * 2;
        #pragma unroll
        for (int kk = 0; kk < BKH; kk += 16) {
            unsigned af[4][4], bf[4][2];
            #pragma unroll
            for (int mt = 0; mt < 4; mt++)
                ldmatrix_x4(af[mt], aoff[mt] + stage_off + kk * 2);
            #pragma unroll
            for (int np = 0; np < 2; np++) {
                unsigned r[4];
                ldmatrix_x4(r, boff[np] + stage_off + kk * 2);
                bf[np * 2][0]     = r[0];
                bf[np * 2 + 1][0] = r[1];
                bf[np * 2][1]     = r[2];
                bf[np * 2 + 1][1] = r[3];
            }
            #pragma unroll
            for (int mt = 0; mt < 4; mt++)
                #pragma unroll
                for (int nt = 0; nt < 4; nt++)
                    mma_fp16(acc[mt][nt], af[mt], bf[nt]);
        }
        cur = (cur + 1 == STAGES) ? 0 : cur + 1;
        nxt = (nxt + 1 == STAGES) ? 0 : nxt + 1;
    }

    #pragma unroll
    for (int mt = 0; mt < 4; mt++) {
        const int row0 = bm + m0 + mt * 16 + g;
        #pragma unroll
        for (int nt = 0; nt < 4; nt++) {
            const int col = bn + n0 + nt * 8 + 2 * t;
            const float bv0 = bias[col], bv1 = bias[col + 1];
            float v00 = acc[mt][nt][0] + bv0;
            float v01 = acc[mt][nt][1] + bv1;
            float v10 = acc[mt][nt][2] + bv0;
            float v11 = acc[mt][nt][3] + bv1;
            if (EPI == 1) {
                v00 = fminf((v00 > 20.f) ? v00 : log1pf(__expf(v00)), 1.0f);
                v01 = fminf((v01 > 20.f) ? v01 : log1pf(__expf(v01)), 1.0f);
                v10 = fminf((v10 > 20.f) ? v10 : log1pf(__expf(v10)), 1.0f);
                v11 = fminf((v11 > 20.f) ? v11 : log1pf(__expf(v11)), 1.0f);
            } else if (EPI == 2) {
                v00 += res[(size_t)row0 * ldres + col];
                v01 += res[(size_t)row0 * ldres + col + 1];
                v10 += res[(size_t)(row0 + 8) * ldres + col];
                v11 += res[(size_t)(row0 + 8) * ldres + col + 1];
            }
            if (OUTH) {
                __half* C = (__half*)Cv;
                *(__half2*)(C + (size_t)row0 * ldc + col)       = __floats2half2_rn(v00, v01);
                *(__half2*)(C + (size_t)(row0 + 8) * ldc + col) = __floats2half2_rn(v10, v11);
            } else {
                float* C = (float*)Cv;
                *(float2*)(C + (size_t)row0 * ldc + col)       = make_float2(v00, v01);
                *(float2*)(C + (size_t)(row0 + 8) * ldc + col) = make_float2(v10, v11);
            }
        }
    }
    #undef AS
    #undef BS
}

// -------------------- weight fp32 -> fp16 conversion ------------------------
__global__ void __launch_bounds__(256) cvt_kernel(
    const float4* __restrict__ src, __half* __restrict__ dst, int n4)
{
    int i = blockIdx.x * blockDim.x + threadIdx.x;
    int stride = gridDim.x * blockDim.x;
    for (; i < n4; i += stride) {
        float4 v = src[i];
        __half2 lo = __floats2half2_rn(v.x, v.y);
        __half2 hi = __floats2half2_rn(v.z, v.w);
        *(__half2*)(dst + i * 4)     = lo;
        *(__half2*)(dst + i * 4 + 2) = hi;
    }
}

// -------------------- A-power table: A, A^2/2, A^3/6 ------------------------
__global__ void __launch_bounds__(256) apow_kernel(
    const float* __restrict__ A, float* __restrict__ APOW)
{
    int i = blockIdx.x * 256 + threadIdx.x;
    if (i < NSTATE * DIM) {
        int n = i >> 11;           // /DIM
        int d = i & (DIM - 1);
        float a = A[i];
        APOW[(n * 3 + 0) * DIM + d] = a;
        APOW[(n * 3 + 1) * DIM + d] = 0.5f * a * a;
        APOW[(n * 3 + 2) * DIM + d] = (1.0f / 6.0f) * a * a * a;
    }
}

// -------------------- LayerNorm (fp16 output) -------------------------------
__global__ void __launch_bounds__(256) ln_kernel(
    const float* __restrict__ x,
    const float* __restrict__ gamma,
    const float* __restrict__ beta,
    __half* __restrict__ out)
{
    const int token = blockIdx.x;
    const float* xp = x + (size_t)token * DIM;
    __half* op = out + (size_t)token * DIM;
    const int base = threadIdx.x * 8;

    float4 a = *(const float4*)(xp + base);
    float4 b = *(const float4*)(xp + base + 4);

    float s  = a.x + a.y + a.z + a.w + b.x + b.y + b.z + b.w;
    float ss = a.x*a.x + a.y*a.y + a.z*a.z + a.w*a.w
             + b.x*b.x + b.y*b.y + b.z*b.z + b.w*b.w;

    #pragma unroll
    for (int o = 16; o > 0; o >>= 1) {
        s  += __shfl_down_sync(0xffffffffu, s,  o);
        ss += __shfl_down_sync(0xffffffffu, ss, o);
    }
    __shared__ float sbuf[8], ssbuf[8];
    const int warp = threadIdx.x >> 5, lane = threadIdx.x & 31;
    if (lane == 0) { sbuf[warp] = s; ssbuf[warp] = ss; }
    __syncthreads();
    __shared__ float s_mean, s_rstd;
    if (threadIdx.x == 0) {
        float ts = 0.f, tss = 0.f;
        #pragma unroll
        for (int w = 0; w < 8; w++) { ts += sbuf[w]; tss += ssbuf[w]; }
        float mean = ts * (1.0f / DIM);
        float var  = tss * (1.0f / DIM) - mean * mean;
        s_mean = mean;
        s_rstd = rsqrtf(var + LN_EPS);
    }
    __syncthreads();
    const float mean = s_mean, rstd = s_rstd;

    float4 g0 = *(const float4*)(gamma + base);
    float4 g1 = *(const float4*)(gamma + base + 4);
    float4 bt0 = *(const float4*)(beta + base);
    float4 bt1 = *(const float4*)(beta + base + 4);

    __half2 h0 = __floats2half2_rn((a.x - mean) * rstd * g0.x + bt0.x,
                                   (a.y - mean) * rstd * g0.y + bt0.y);
    __half2 h1 = __floats2half2_rn((a.z - mean) * rstd * g0.z + bt0.z,
                                   (a.w - mean) * rstd * g0.w + bt0.w);
    __half2 h2 = __floats2half2_rn((b.x - mean) * rstd * g1.x + bt1.x,
                                   (b.y - mean) * rstd * g1.y + bt1.y);
    __half2 h3 = __floats2half2_rn((b.z - mean) * rstd * g1.z + bt1.z,
                                   (b.w - mean) * rstd * g1.w + bt1.w);
    uint4 pk;
    pk.x = *(unsigned*)&h0; pk.y = *(unsigned*)&h1;
    pk.z = *(unsigned*)&h2; pk.w = *(unsigned*)&h3;
    *(uint4*)(op + base) = pk;
}

// -------------------- fused B/C proj + SSM + gate (8 tokens/block) ----------
// Taylor: exp(a*dt) ~ 1 + a*dt + (a*dt)^2/2 + (a*dt)^3/6  (|a*dt| < 0.05)
// y[d] = s0 + dt*(s1 + dt*(s2 + dt*s3)),  sk = sum_n coef[n]*A^k-table[n][d]
#define TPB 8   // tokens per block

__global__ void __launch_bounds__(256) bcssm_kernel(
    const __half* __restrict__ xz, int ld,
    const __half* __restrict__ dt,
    const float* __restrict__ APOW,
    const float* __restrict__ W_B, const float* __restrict__ b_B,
    const float* __restrict__ W_C, const float* __restrict__ b_C,
    __half* __restrict__ gated)
{
    __shared__ __half xs[TPB][DIM];          // 32 KB
    __shared__ float coef[TPB][NSTATE];
    __shared__ float s0[TPB];

    const int tok0 = blockIdx.x * TPB;
    const int tid = threadIdx.x;
    const int warp = tid >> 5, lane = tid & 31;

    // phase 0: stage x_ssm for 8 tokens (fp16)
    for (int i = tid; i < TPB * DIM / 8; i += 256) {
        const int row = i >> 8;              // i / 256
        const int col = (i & 255) * 8;
        *(uint4*)&xs[row][col] = *(const uint4*)(xz + (size_t)(tok0 + row) * ld + col);
    }
    __syncthreads();

    // phase 1: coef[t][n] = (x.W_B[n]+bB)*(x.W_C[n]+bC); warp w owns n={2w,2w+1}
    {
        const int n0 = warp * 2, n1 = n0 + 1;
        const float* wb0 = W_B + (size_t)n0 * DIM;
        const float* wb1 = W_B + (size_t)n1 * DIM;
        const float* wc0 = W_C + (size_t)n0 * DIM;
        const float* wc1 = W_C + (size_t)n1 * DIM;

        float aB0[TPB], aB1[TPB], aC0[TPB], aC1[TPB];
        #pragma unroll
        for (int t = 0; t < TPB; t++) { aB0[t]=0.f; aB1[t]=0.f; aC0[t]=0.f; aC1[t]=0.f; }

        for (int d = lane * 4; d < DIM; d += 128) {
            float4 b0 = *(const float4*)(wb0 + d);
            float4 b1 = *(const float4*)(wb1 + d);
            float4 c0 = *(const float4*)(wc0 + d);
            float4 c1 = *(const float4*)(wc1 + d);
            #pragma unroll
            for (int t = 0; t < TPB; t++) {
                float2 f0 = __half22float2(*(const __half2*)&xs[t][d]);
                float2 f1 = __half22float2(*(const __half2*)&xs[t][d + 2]);
                aB0[t] += f0.x*b0.x + f0.y*b0.y + f1.x*b0.z + f1.y*b0.w;
                aB1[t] += f0.x*b1.x + f0.y*b1.y + f1.x*b1.z + f1.y*b1.w;
                aC0[t] += f0.x*c0.x + f0.y*c0.y + f1.x*c0.z + f1.y*c0.w;
                aC1[t] += f0.x*c1.x + f0.y*c1.y + f1.x*c1.z + f1.y*c1.w;
            }
        }
        #pragma unroll
        for (int t = 0; t < TPB; t++) {
            #pragma unroll
            for (int o = 16; o > 0; o >>= 1) {
                aB0[t] += __shfl_down_sync(0xffffffffu, aB0[t], o);
                aB1[t] += __shfl_down_sync(0xffffffffu, aB1[t], o);
                aC0[t] += __shfl_down_sync(0xffffffffu, aC0[t], o);
                aC1[t] += __shfl_down_sync(0xffffffffu, aC1[t], o);
            }
        }
        if (lane == 0) {
            const float bB0 = b_B[n0], bB1 = b_B[n1], bC0 = b_C[n0], bC1 = b_C[n1];
            #pragma unroll
            for (int t = 0; t < TPB; t++) {
                coef[t][n0] = (aB0[t] + bB0) * (aC0[t] + bC0);
                coef[t][n1] = (aB1[t] + bB1) * (aC1[t] + bC1);
            }
        }
    }
    __syncthreads();
    if (tid < TPB) {
        float s = 0.f;
        #pragma unroll
        for (int n = 0; n < NSTATE; n++) s += coef[tid][n];
        s0[tid] = s;
    }
    __syncthreads();

    // phase 2: SSM polynomial + silu gate
    for (int d = tid; d < DIM; d += 256) {
        float a1[NSTATE], a2[NSTATE], a3[NSTATE];
        #pragma unroll
        for (int n = 0; n < NSTATE; n++) {
            a1[n] = APOW[(n * 3 + 0) * DIM + d];
            a2[n] = APOW[(n * 3 + 1) * DIM + d];
            a3[n] = APOW[(n * 3 + 2) * DIM + d];
        }
        #pragma unroll
        for (int t = 0; t < TPB; t++) {
            float s1 = 0.f, s2 = 0.f, s3 = 0.f;
            #pragma unroll
            for (int n = 0; n < NSTATE; n++) {
                const float cn = coef[t][n];
                s1 += cn * a1[n];
                s2 += cn * a2[n];
                s3 += cn * a3[n];
            }
            const size_t rowoff = (size_t)(tok0 + t);
            const float dtd = __half2float(dt[rowoff * DIM + d]);
            const float y = s0[t] + dtd * (s1 + dtd * (s2 + dtd * s3));
            const float xv = __half2float(xs[t][d]);
            const float zv = __half2float(xz[rowoff * ld + DIM + d]);
            const float sig = 1.0f / (1.0f + __expf(-zv));
            gated[rowoff * DIM + d] = __float2half_rn(y * xv * zv * sig);
        }
    }
}

// -------------------- launch ------------------------------------------------
extern "C" void kernel_launch(void* const* d_in, const int* in_sizes, int n_in,
                              void* d_out, int out_size)
{
    const float* x        = (const float*)d_in[0];
    const float* ln_gamma = (const float*)d_in[1];
    const float* ln_beta  = (const float*)d_in[2];
    const float* W_in     = (const float*)d_in[3];
    const float* b_in     = (const float*)d_in[4];
    const float* state_A  = (const float*)d_in[5];
    const float* W_B      = (const float*)d_in[6];
    const float* b_B      = (const float*)d_in[7];
    const float* W_C      = (const float*)d_in[8];
    const float* b_C      = (const float*)d_in[9];
    const float* W_dt     = (const float*)d_in[10];
    const float* b_dt     = (const float*)d_in[11];
    const float* W_out    = (const float*)d_in[12];
    const float* b_out    = (const float*)d_in[13];
    float* out = (float*)d_out;

    __half *xn, *xz, *dt, *gated, *win, *wdt, *wout;
    float *apow;
    cudaGetSymbolAddress((void**)&xn,    g_xn);
    cudaGetSymbolAddress((void**)&xz,    g_xz);
    cudaGetSymbolAddress((void**)&dt,    g_dt);
    cudaGetSymbolAddress((void**)&gated, g_gated);
    cudaGetSymbolAddress((void**)&win,   g_win);
    cudaGetSymbolAddress((void**)&wdt,   g_wdt);
    cudaGetSymbolAddress((void**)&wout,  g_wout);
    cudaGetSymbolAddress((void**)&apow,  g_apow);

    static bool attr_done = false;
    if (!attr_done) {
        cudaFuncSetAttribute(gemm_fp16<0,1>, cudaFuncAttributeMaxDynamicSharedMemorySize, SM_TOTAL_BYTES);
        cudaFuncSetAttribute(gemm_fp16<1,1>, cudaFuncAttributeMaxDynamicSharedMemorySize, SM_TOTAL_BYTES);
        cudaFuncSetAttribute(gemm_fp16<2,0>, cudaFuncAttributeMaxDynamicSharedMemorySize, SM_TOTAL_BYTES);
        attr_done = true;
    }

    // 0. prep: weights -> fp16, A power table
    cvt_kernel<<<1024, 256>>>((const float4*)W_in,  win,  TWO_DIM * DIM / 4);
    cvt_kernel<<<512,  256>>>((const float4*)W_dt,  wdt,  DIM * DIM / 4);
    cvt_kernel<<<512,  256>>>((const float4*)W_out, wout, DIM * DIM / 4);
    apow_kernel<<<(NSTATE * DIM + 255) / 256, 256>>>(state_A, apow);

    // 1. LayerNorm (fp16 output)
    ln_kernel<<<TOKENS, 256>>>(x, ln_gamma, ln_beta, xn);

    // 2. xz = xn @ W_in^T + b_in  -> fp16
    gemm_fp16<0, 1><<<dim3(TWO_DIM / BN, TOKENS / BM), 256, SM_TOTAL_BYTES>>>(
        xn, DIM, win, DIM, b_in, nullptr, 0, xz, TWO_DIM, DIM);

    // 3. dt = min(softplus(x_ssm @ W_dt^T + b_dt), 1) -> fp16
    gemm_fp16<1, 1><<<dim3(DIM / BN, TOKENS / BM), 256, SM_TOTAL_BYTES>>>(
        xz, TWO_DIM, wdt, DIM, b_dt, nullptr, 0, dt, DIM, DIM);

    // 4+5. coef + gated fused (Taylor SSM) -> fp16
    bcssm_kernel<<<TOKENS / TPB, 256>>>(xz, TWO_DIM, dt, apow, W_B, b_B, W_C, b_C, gated);

    // 6. out = gated @ W_out^T + b_out + residual(x) -> fp32
    gemm_fp16<2, 0><<<dim3(DIM / BN, TOKENS / BM), 256, SM_TOTAL_BYTES>>>(
        gated, DIM, wout, DIM, b_out, x, DIM, out, DIM, DIM);
}